// round 10
// baseline (speedup 1.0000x reference)
#include <cuda_runtime.h>
#include <cstdint>
#include <cstddef>

#define BB 128
#define TT 256
#define EMBD 200
#define NU1 400
#define NU2 200
#define KP1 (NU1 + 4)
#define KP2 (NU2 + 4)

// output layout: out2 | out1 | h2 | h1
#define OUT2_OFF 0
#define OUT1_OFF (BB*TT*NU2)
#define H2_OFF   (OUT1_OFF + BB*TT*NU1)
#define H1_OFF   (H2_OFF + BB*NU2)

__device__ float g_xn [(size_t)BB*TT*EMBD];
__device__ float g_xw1[(size_t)BB*TT*3*NU1];
__device__ float g_xw2[(size_t)BB*TT*3*NU2];
__device__ float g_o1t[(size_t)BB*TT*NU1];   // out1 transposed [t][u][b]
__device__ float g_o2t[(size_t)BB*TT*NU2];   // out2 transposed [t][u][b]
__device__ float g_h1 [2*BB*KP1];            // padded rows -> bulk-copyable
__device__ float g_h2 [2*BB*KP2];
__device__ unsigned g_cnt1[4*32], g_gen1[4*32], g_cnt2[4*32], g_gen2[4*32];

// ---- async helpers ----
__device__ __forceinline__ void cp_async16(uint32_t s, const void* g)
{
    asm volatile("cp.async.cg.shared.global [%0], [%1], 16;" :: "r"(s), "l"(g));
}
__device__ __forceinline__ void cp_commit() { asm volatile("cp.async.commit_group;"); }
__device__ __forceinline__ void cp_wait0()  { asm volatile("cp.async.wait_all;"); }

__device__ __forceinline__ void mbar_init(uint32_t mbar)
{
    asm volatile("mbarrier.init.shared.b64 [%0], 1;" :: "r"(mbar) : "memory");
}
__device__ __forceinline__ void mbar_expect_tx(uint32_t mbar, uint32_t bytes)
{
    asm volatile("mbarrier.arrive.expect_tx.shared.b64 _, [%0], %1;"
                 :: "r"(mbar), "r"(bytes) : "memory");
}
__device__ __forceinline__ void mbar_wait(uint32_t mbar, uint32_t parity)
{
    uint32_t done;
    asm volatile(
        "{\n\t.reg .pred p;\n\t"
        "mbarrier.try_wait.parity.acquire.cta.shared::cta.b64 p, [%1], %2;\n\t"
        "selp.b32 %0, 1, 0, p;\n\t}"
        : "=r"(done) : "r"(mbar), "r"(parity) : "memory");
    if (!done) {
        asm volatile(
            "{\n\t.reg .pred P1;\n\t"
            "WAIT_LOOP_%=:\n\t"
            "mbarrier.try_wait.parity.acquire.cta.shared::cta.b64 P1, [%0], %1, 0x989680;\n\t"
            "@P1 bra.uni WAIT_DONE_%=;\n\t"
            "bra.uni WAIT_LOOP_%=;\n\t"
            "WAIT_DONE_%=:\n\t}"
            :: "r"(mbar), "r"(parity) : "memory");
    }
}
__device__ __forceinline__ void bulk_g2s(uint32_t dst, const void* src, uint32_t bytes,
                                         uint32_t mbar)
{
    asm volatile("cp.async.bulk.shared::cluster.global.mbarrier::complete_tx::bytes "
                 "[%0], [%1], %2, [%3];"
                 :: "r"(dst), "l"(src), "r"(bytes), "r"(mbar) : "memory");
}
__device__ __forceinline__ void fence_async()
{
    asm volatile("fence.proxy.async;" ::: "memory");
}

// packed f32x2 ops (sm_10x)
__device__ __forceinline__ unsigned long long fma2(unsigned long long a, unsigned long long b,
                                                   unsigned long long c)
{
    unsigned long long d;
    asm("fma.rn.f32x2 %0, %1, %2, %3;" : "=l"(d) : "l"(a), "l"(b), "l"(c));
    return d;
}
__device__ __forceinline__ unsigned long long pack2(float lo, float hi)
{
    unsigned long long d;
    asm("mov.b64 %0, {%1, %2};" : "=l"(d) : "f"(lo), "f"(hi));
    return d;
}
__device__ __forceinline__ float hsum2(unsigned long long a)
{
    float2 f = *reinterpret_cast<float2*>(&a);
    return f.x + f.y;
}
__device__ __forceinline__ float2 unpack2(unsigned long long a)
{
    return *reinterpret_cast<float2*>(&a);
}

__global__ void embed_bn(const int* __restrict__ tokens, const float* __restrict__ emb,
                         const float* __restrict__ gamma, const float* __restrict__ beta,
                         const float* __restrict__ mmean, const float* __restrict__ mvar)
{
    int idx = blockIdx.x * blockDim.x + threadIdx.x;
    if (idx >= BB*TT*EMBD) return;
    int d = idx % EMBD;
    int m = idx / EMBD;              // m = t*128 + b
    int b = m & (BB-1), t = m >> 7;
    int tok = tokens[b*TT + t];
    float s = gamma[d] * rsqrtf(mvar[d] + 1e-3f);
    g_xn[idx] = (emb[(size_t)tok*EMBD + d] - mmean[d]) * s + beta[d];
}

__global__ void init_state()
{
    int i = blockIdx.x * blockDim.x + threadIdx.x;
    if (i < 2*BB*KP1) g_h1[i] = 0.f;
    if (i < 2*BB*KP2) g_h2[i] = 0.f;
    if (i < 4*32) { g_cnt1[i] = 0; g_gen1[i] = 0; g_cnt2[i] = 0; g_gen2[i] = 0; }
}

// copy padded h [BB][KP] -> dense [BB][U]
__global__ void copy_h_strided(const float* __restrict__ src, float* __restrict__ dst,
                               int U, int KP)
{
    int i = blockIdx.x * blockDim.x + threadIdx.x;
    if (i < BB*U) dst[i] = src[(i/U)*KP + (i % U)];
}

// transpose src [TT][U][BB] -> dst [BB][TT][U]; grid (TT, ceil(U/32), BB/32), block (32,8)
__global__ void transpose_tub(const float* __restrict__ src, float* __restrict__ dst, int U)
{
    __shared__ float s[32][33];
    int t = blockIdx.x, u0 = blockIdx.y*32, b0 = blockIdx.z*32;
    int xi = threadIdx.x, yj = threadIdx.y;
    for (int i = yj; i < 32; i += 8) {
        int u = u0 + i;
        if (u < U) s[i][xi] = src[((size_t)t*U + u)*BB + b0 + xi];
    }
    __syncthreads();
    for (int i = yj; i < 32; i += 8) {
        int u = u0 + xi;
        if (u < U) dst[((size_t)(b0 + i)*TT + t)*U + u] = s[xi][i];
    }
}

// ---------------- SGEMM: C[M,N] = A @ B + bias, 128x128 tile, 8x8/thread, f32x2 ----------------
template<int ALAY>
__global__ void __launch_bounds__(256, 2)
sgemm128(const float* __restrict__ A, const float* __restrict__ Bw,
         const float* __restrict__ bias, float* __restrict__ C, int N, int K)
{
    constexpr int AP = 132, BP = 132;
    __shared__ float As[2][8][AP];
    __shared__ float Bs[2][8][BP];
    const int tid = threadIdx.x;
    const int col0 = blockIdx.x * 128;
    const int row0 = blockIdx.y * 128;
    const int tx = tid & 15, ty = tid >> 4;

    for (int i = tid; i < 2*8*BP; i += 256) (&Bs[0][0][0])[i] = 0.f;
    __syncthreads();

    const int bkk = tid >> 5, bnq = (tid & 31) * 4;
    const int bgc = col0 + bnq;
    uint32_t bs_s0 = (uint32_t)__cvta_generic_to_shared(&Bs[0][bkk][bnq]);
    uint32_t bs_s1 = (uint32_t)__cvta_generic_to_shared(&Bs[1][bkk][bnq]);

    float4 rA;
    auto loadA = [&](int k0) {
        if (ALAY == 0) {
            int m = tid >> 1, kq = (tid & 1) * 4;
            rA = *reinterpret_cast<const float4*>(A + (size_t)(row0 + m)*K + k0 + kq);
        } else {
            int kk = tid >> 5, bq = (tid & 31) * 4;
            rA = *reinterpret_cast<const float4*>(A + ((size_t)blockIdx.y*K + k0 + kk)*128 + bq);
        }
    };
    auto stsA = [&](int buf) {
        if (ALAY == 0) {
            int m = tid >> 1, kq = (tid & 1) * 4;
            As[buf][kq+0][m] = rA.x; As[buf][kq+1][m] = rA.y;
            As[buf][kq+2][m] = rA.z; As[buf][kq+3][m] = rA.w;
        } else {
            int kk = tid >> 5, bq = (tid & 31) * 4;
            *reinterpret_cast<float4*>(&As[buf][kk][bq]) = rA;
        }
    };
    auto asyncB = [&](int k0, int buf) {
        if (bgc < N)
            cp_async16(buf ? bs_s1 : bs_s0, Bw + (size_t)(k0 + bkk)*N + bgc);
    };

    loadA(0);
    asyncB(0, 0);
    cp_commit();

    unsigned long long acc[4][8] = {};
    const int NC = K / 8;
    for (int c = 0; c < NC; c++) {
        int buf = c & 1;
        cp_wait0();
        stsA(buf);
        __syncthreads();
        if (c + 1 < NC) {
            loadA((c+1)*8);
            asyncB((c+1)*8, buf ^ 1);
            cp_commit();
        }
#pragma unroll
        for (int kk = 0; kk < 8; kk++) {
            ulonglong2 a01 = *reinterpret_cast<const ulonglong2*>(&As[buf][kk][ty*8]);
            ulonglong2 a23 = *reinterpret_cast<const ulonglong2*>(&As[buf][kk][ty*8 + 4]);
            float4 b0 = *reinterpret_cast<const float4*>(&Bs[buf][kk][tx*4]);
            float4 b1 = *reinterpret_cast<const float4*>(&Bs[buf][kk][64 + tx*4]);
            unsigned long long ap[4] = {a01.x, a01.y, a23.x, a23.y};
            unsigned long long bd[8];
            bd[0] = pack2(b0.x, b0.x); bd[1] = pack2(b0.y, b0.y);
            bd[2] = pack2(b0.z, b0.z); bd[3] = pack2(b0.w, b0.w);
            bd[4] = pack2(b1.x, b1.x); bd[5] = pack2(b1.y, b1.y);
            bd[6] = pack2(b1.z, b1.z); bd[7] = pack2(b1.w, b1.w);
#pragma unroll
            for (int r = 0; r < 4; r++)
#pragma unroll
                for (int cc = 0; cc < 8; cc++)
                    acc[r][cc] = fma2(ap[r], bd[cc], acc[r][cc]);
        }
        __syncthreads();
    }

#pragma unroll
    for (int r = 0; r < 4; r++) {
        size_t gr = row0 + ty*8 + r*2;
#pragma unroll
        for (int cc = 0; cc < 8; cc++) {
            int gc = col0 + (cc < 4 ? tx*4 + cc : 64 + tx*4 + (cc - 4));
            if (gc < N) {
                float2 v = unpack2(acc[r][cc]);
                float bv = bias[gc];
                C[gr*N + gc]       = v.x + bv;
                C[(gr + 1)*N + gc] = v.y + bv;
            }
        }
    }
}

// ---------------- persistent GRU layer: bulk h-exchange ----------------
// grid (UNITS/UT, BB/32). CTA: UT units x 32 batches; warp = UW units x 32 batches (lane=batch).
// h global buffers padded [BB][KP]; per step ONE cp.async.bulk stages the whole h tile.
template<int UNITS, int UT, int UW, int GROUP_CTAS>
__global__ void __launch_bounds__(32*UT/UW, 1)
gru_layer(const float* __restrict__ xw, const float* __restrict__ Ur,
          const float* __restrict__ br, const int* __restrict__ tokens,
          float* __restrict__ outT, float* __restrict__ hping,
          unsigned* cnt, unsigned* gen)
{
    constexpr int NTHR = 32*UT/UW;
    constexpr int KP = UNITS + 4;
    constexpr int XS = 3*UT;
    constexpr uint32_t HBYTES = 32*KP*4;
    extern __shared__ float sm[];
    float*    sU    = sm;                        // [UT*3][KP]
    float*    sH    = sU + UT*3*KP;              // [32][KP]  (bulk dst, 128B aligned)
    float*    sX    = sH + 32*KP;                // [2][32][XS]
    unsigned* sMask = (unsigned*)(sX + 2*32*XS); // [32][8]
    uint32_t  mbar  = (uint32_t)__cvta_generic_to_shared(sMask + 32*8);

    const int tid  = threadIdx.x;
    const int w    = tid >> 5;
    const int lane = tid & 31;
    const int u0   = blockIdx.x * UT;
    const int b0   = blockIdx.y * 32;
    const int grp  = blockIdx.y;
    const int b    = b0 + lane;
    const int uu0  = u0 + w*UW;

    // one-time: U slice -> smem [unit][gate][k]
    for (int i = tid; i < 3*UT*UNITS; i += NTHR) {
        int k = i / (3*UT), c = i % (3*UT);
        int g = c / UT, lu = c % UT;
        sU[(lu*3 + g)*KP + k] = Ur[(size_t)k*(3*UNITS) + g*UNITS + u0 + lu];
    }
    // one-time: bit-packed mask
    for (int i = tid; i < 32*8; i += NTHR) {
        int bb = i >> 3, wd = i & 7;
        unsigned m = 0;
        for (int j = 0; j < 32; j++)
            m |= (tokens[(b0 + bb)*TT + wd*32 + j] != 0 ? 1u : 0u) << j;
        sMask[bb*8 + wd] = m;
    }
    // stage sX buffer 0 for t=0 (16B ops)
    const uint32_t sX_s = (uint32_t)__cvta_generic_to_shared(sX);
    {
        for (int i = tid; i < 32*(XS/4); i += NTHR) {
            int bb = i / (XS/4), q = i % (XS/4);
            int g = q / (UT/4), l4 = q % (UT/4);
            cp_async16(sX_s + (uint32_t)(bb*XS + g*UT + l4*4)*4,
                       xw + (size_t)(b0 + bb)*(3*UNITS) + (size_t)g*UNITS + u0 + l4*4);
        }
        cp_commit();
    }
    if (tid == 0) mbar_init(mbar);
    __syncthreads();
    if (tid == 0) {                      // kick off h(0) bulk (buffer 0, zeroed)
        mbar_expect_tx(mbar, HBYTES);
        bulk_g2s((uint32_t)__cvta_generic_to_shared(sH),
                 hping + (size_t)b0*KP, HBYTES, mbar);
    }

    float bz[UW], brr[UW], bh[UW];
#pragma unroll
    for (int j = 0; j < UW; j++) {
        bz[j]  = br[uu0 + j];
        brr[j] = br[UNITS + uu0 + j];
        bh[j]  = br[2*UNITS + uu0 + j];
    }

    const float* hrow = sH + lane*KP;
    const uint32_t sH_s = (uint32_t)__cvta_generic_to_shared(sH);

    for (int t = 0; t < TT; t++) {
        float* hn = hping + (size_t)((t + 1) & 1)*BB*KP;
        const float* sXc = sX + (t & 1)*32*XS;

        mbar_wait(mbar, (uint32_t)(t & 1));  // h tile landed
        cp_wait0();                          // own xw cp.async groups landed
        __syncthreads();                     // cross-thread visibility of sX

        unsigned long long az[UW] = {}, ar[UW] = {}, ah[UW] = {};
#pragma unroll 4
        for (int k = 0; k < UNITS; k += 4) {
            ulonglong2 h2 = *reinterpret_cast<const ulonglong2*>(hrow + k);
#pragma unroll
            for (int j = 0; j < UW; j++) {
                const float* ub = sU + ((w*UW + j)*3)*KP + k;
                ulonglong2 uz = *reinterpret_cast<const ulonglong2*>(ub);
                ulonglong2 ur = *reinterpret_cast<const ulonglong2*>(ub + KP);
                ulonglong2 uh = *reinterpret_cast<const ulonglong2*>(ub + 2*KP);
                az[j] = fma2(h2.x, uz.x, az[j]); az[j] = fma2(h2.y, uz.y, az[j]);
                ar[j] = fma2(h2.x, ur.x, ar[j]); ar[j] = fma2(h2.y, ur.y, ar[j]);
                ah[j] = fma2(h2.x, uh.x, ah[j]); ah[j] = fma2(h2.y, uh.y, ah[j]);
            }
        }

        const int mk = (sMask[lane*8 + (t >> 5)] >> (t & 31)) & 1;
        float hv[UW];
#pragma unroll
        for (int j = 0; j < UW; j++) {
            float vz = hsum2(az[j]), vr = hsum2(ar[j]), vh = hsum2(ah[j]);
            int lu = w*UW + j;
            float xz = sXc[lane*XS + lu];
            float xr = sXc[lane*XS + UT + lu];
            float xh = sXc[lane*XS + 2*UT + lu];
            float z  = 1.f / (1.f + __expf(-(xz + vz + bz[j])));
            float r  = 1.f / (1.f + __expf(-(xr + vr + brr[j])));
            float hh = tanhf(xh + r * (vh + bh[j]));
            float hold = hrow[uu0 + j];
            float hnew = z*hold + (1.f - z)*hh;
            hv[j] = mk ? hnew : hold;
        }
        if constexpr (UW == 2) {
            float2 v = make_float2(hv[0], hv[1]);
            *reinterpret_cast<float2*>(hn + (size_t)b*KP + uu0) = v;
            outT[((size_t)t*UNITS + uu0    )*BB + b] = hv[0];
            outT[((size_t)t*UNITS + uu0 + 1)*BB + b] = hv[1];
        } else {
            hn[(size_t)b*KP + uu0] = hv[0];
            outT[((size_t)t*UNITS + uu0)*BB + b] = hv[0];
        }

        // prefetch xw(t+1) (other sX buffer) across the barrier
        if (t + 1 < TT) {
            uint32_t dst = sX_s + (uint32_t)(((t+1) & 1)*32*XS)*4;
            for (int i = tid; i < 32*(XS/4); i += NTHR) {
                int bb = i / (XS/4), q = i % (XS/4);
                int g = q / (UT/4), l4 = q % (UT/4);
                cp_async16(dst + (uint32_t)(bb*XS + g*UT + l4*4)*4,
                           xw + ((size_t)(t+1)*BB + b0 + bb)*(size_t)(3*UNITS)
                              + (size_t)g*UNITS + u0 + l4*4);
            }
            cp_commit();
        }

        __syncthreads();                     // all compute done; sH reusable after this
        if (tid == 0) {
            unsigned* c = cnt + grp*32;
            unsigned* g = gen + grp*32;
            unsigned target = (unsigned)(t + 1);
            unsigned arr;
            asm volatile("atom.release.gpu.global.add.u32 %0, [%1], 1;"
                         : "=r"(arr) : "l"(c) : "memory");
            if (arr == (unsigned)(GROUP_CTAS - 1)) {
                asm volatile("st.relaxed.gpu.global.u32 [%0], 0;" :: "l"(c) : "memory");
                asm volatile("st.release.gpu.global.u32 [%0], %1;" :: "l"(g), "r"(target) : "memory");
            } else {
                unsigned gv;
                do {
                    asm volatile("ld.acquire.gpu.global.u32 %0, [%1];"
                                 : "=r"(gv) : "l"(g) : "memory");
                } while (gv < target);
            }
            if (t + 1 < TT) {                // h(t+1) complete group-wide: launch bulk now
                fence_async();
                mbar_expect_tx(mbar, HBYTES);
                bulk_g2s(sH_s, hping + (size_t)(((t+1) & 1)*BB + b0)*KP, HBYTES, mbar);
            }
        }
        // non-elected threads fall through to next iteration's mbar_wait
    }
}

extern "C" void kernel_launch(void* const* d_in, const int* in_sizes, int n_in,
                              void* d_out, int out_size)
{
    const int*   tokens = (const int*)  d_in[0];
    const float* emb    = (const float*)d_in[1];
    const float* gamma  = (const float*)d_in[2];
    const float* beta   = (const float*)d_in[3];
    const float* mmean  = (const float*)d_in[4];
    const float* mvar   = (const float*)d_in[5];
    const float* W1     = (const float*)d_in[6];
    const float* Ur1    = (const float*)d_in[7];
    const float* b1     = (const float*)d_in[8];
    const float* W2     = (const float*)d_in[9];
    const float* Ur2    = (const float*)d_in[10];
    const float* b2     = (const float*)d_in[11];

    float* out  = (float*)d_out;
    float* out2 = out + OUT2_OFF;
    float* out1 = out + OUT1_OFF;
    float* h2o  = out + H2_OFF;
    float* h1o  = out + H1_OFF;

    void *p_xn, *p_xw1, *p_xw2, *p_o1t, *p_o2t, *p_h1, *p_h2, *p_c1, *p_g1, *p_c2, *p_g2;
    cudaGetSymbolAddress(&p_xn,  g_xn);
    cudaGetSymbolAddress(&p_xw1, g_xw1);
    cudaGetSymbolAddress(&p_xw2, g_xw2);
    cudaGetSymbolAddress(&p_o1t, g_o1t);
    cudaGetSymbolAddress(&p_o2t, g_o2t);
    cudaGetSymbolAddress(&p_h1,  g_h1);
    cudaGetSymbolAddress(&p_h2,  g_h2);
    cudaGetSymbolAddress(&p_c1,  g_cnt1);
    cudaGetSymbolAddress(&p_g1,  g_gen1);
    cudaGetSymbolAddress(&p_c2,  g_cnt2);
    cudaGetSymbolAddress(&p_g2,  g_gen2);
    float* xn  = (float*)p_xn;
    float* xw1 = (float*)p_xw1;
    float* xw2 = (float*)p_xw2;
    float* o1t = (float*)p_o1t;
    float* o2t = (float*)p_o2t;
    float* h1p = (float*)p_h1;
    float* h2p = (float*)p_h2;

    constexpr int L1_SMEM = (16*3*KP1 + 32*KP1 + 2*32*48)*4 + 32*8*4 + 16;
    constexpr int L2_SMEM = (8*3*KP2 + 32*KP2 + 2*32*24)*4 + 32*8*4 + 16;

    cudaFuncSetAttribute(gru_layer<NU1, 16, 2, 25>,
                         cudaFuncAttributeMaxDynamicSharedMemorySize, L1_SMEM);
    cudaFuncSetAttribute(gru_layer<NU2, 8, 1, 25>,
                         cudaFuncAttributeMaxDynamicSharedMemorySize, L2_SMEM);

    embed_bn<<<(BB*TT*EMBD + 255)/256, 256>>>(tokens, emb, gamma, beta, mmean, mvar);
    init_state<<<(2*BB*KP1 + 255)/256, 256>>>();

    // xw1 = xn @ W1 + b1[0] : [32768,200] x [200,1200]
    sgemm128<0><<<dim3((3*NU1 + 127)/128, (BB*TT)/128), 256>>>(xn, W1, b1, xw1, 3*NU1, EMBD);

    gru_layer<NU1, 16, 2, 25><<<dim3(NU1/16, BB/32), 256, L1_SMEM>>>(
        xw1, Ur1, b1 + 3*NU1, tokens, o1t, h1p, (unsigned*)p_c1, (unsigned*)p_g1);

    copy_h_strided<<<(BB*NU1 + 255)/256, 256>>>(h1p, h1o, NU1, KP1);  // T even -> buf 0
    transpose_tub<<<dim3(TT, (NU1 + 31)/32, BB/32), dim3(32, 8)>>>(o1t, out1, NU1);

    // xw2 = o1t @ W2 + b2[0] : A layout [t][400][128]
    sgemm128<1><<<dim3((3*NU2 + 127)/128, (BB*TT)/128), 256>>>(o1t, W2, b2, xw2, 3*NU2, NU1);

    gru_layer<NU2, 8, 1, 25><<<dim3(NU2/8, BB/32), 256, L2_SMEM>>>(
        xw2, Ur2, b2 + 3*NU2, tokens, o2t, h2p, (unsigned*)p_c2, (unsigned*)p_g2);

    copy_h_strided<<<(BB*NU2 + 255)/256, 256>>>(h2p, h2o, NU2, KP2);
    transpose_tub<<<dim3(TT, (NU2 + 31)/32, BB/32), dim3(32, 8)>>>(o2t, out2, NU2);
}

// round 11
// speedup vs baseline: 1.0904x; 1.0904x over previous
#include <cuda_runtime.h>
#include <cstdint>
#include <cstddef>

#define BB 128
#define TT 256
#define EMBD 200
#define NU1 400
#define NU2 200

// output layout: out2 | out1 | h2 | h1
#define OUT2_OFF 0
#define OUT1_OFF (BB*TT*NU2)
#define H2_OFF   (OUT1_OFF + BB*TT*NU1)
#define H1_OFF   (H2_OFF + BB*NU2)

__device__ float g_xn [(size_t)BB*TT*EMBD];
__device__ float g_xw1[(size_t)BB*TT*3*NU1];
__device__ float g_o1t[(size_t)BB*TT*NU1];   // out1 [t][u][b]
__device__ float g_o2t[(size_t)BB*TT*NU2];   // out2 [t][u][b]
__device__ float g_h1 [2*BB*NU1];
__device__ float g_h2 [2*BB*NU2];
__device__ unsigned g_cnt1[4*32], g_gen1[4*32], g_cnt2[4*32], g_gen2[4*32];

// ---- cp.async helpers ----
__device__ __forceinline__ void cp_async16(uint32_t s, const void* g)
{
    asm volatile("cp.async.cg.shared.global [%0], [%1], 16;" :: "r"(s), "l"(g));
}
__device__ __forceinline__ void cp_commit() { asm volatile("cp.async.commit_group;"); }
__device__ __forceinline__ void cp_wait0()  { asm volatile("cp.async.wait_all;"); }

// packed f32x2 ops (sm_10x)
__device__ __forceinline__ unsigned long long fma2(unsigned long long a, unsigned long long b,
                                                   unsigned long long c)
{
    unsigned long long d;
    asm("fma.rn.f32x2 %0, %1, %2, %3;" : "=l"(d) : "l"(a), "l"(b), "l"(c));
    return d;
}
__device__ __forceinline__ unsigned long long pack2(float lo, float hi)
{
    unsigned long long d;
    asm("mov.b64 %0, {%1, %2};" : "=l"(d) : "f"(lo), "f"(hi));
    return d;
}
__device__ __forceinline__ float hsum2(unsigned long long a)
{
    float2 f = *reinterpret_cast<float2*>(&a);
    return f.x + f.y;
}
__device__ __forceinline__ float2 unpack2(unsigned long long a)
{
    return *reinterpret_cast<float2*>(&a);
}

// barrier primitives
__device__ __forceinline__ unsigned atom_arrive(unsigned* p)
{
    unsigned arr;
    asm volatile("atom.acq_rel.gpu.global.add.u32 %0, [%1], 1;"
                 : "=r"(arr) : "l"(p) : "memory");
    return arr;
}
__device__ __forceinline__ void st_release(unsigned* p, unsigned v)
{
    asm volatile("st.release.gpu.global.u32 [%0], %1;" :: "l"(p), "r"(v) : "memory");
}
__device__ __forceinline__ void st_relaxed(unsigned* p, unsigned v)
{
    asm volatile("st.relaxed.gpu.global.u32 [%0], %1;" :: "l"(p), "r"(v) : "memory");
}
__device__ __forceinline__ unsigned ld_acquire(const unsigned* p)
{
    unsigned v;
    asm volatile("ld.acquire.gpu.global.u32 %0, [%1];" : "=r"(v) : "l"(p) : "memory");
    return v;
}

__global__ void embed_bn(const int* __restrict__ tokens, const float* __restrict__ emb,
                         const float* __restrict__ gamma, const float* __restrict__ beta,
                         const float* __restrict__ mmean, const float* __restrict__ mvar)
{
    int idx = blockIdx.x * blockDim.x + threadIdx.x;
    if (idx >= BB*TT*EMBD) return;
    int d = idx % EMBD;
    int m = idx / EMBD;              // m = t*128 + b
    int b = m & (BB-1), t = m >> 7;
    int tok = tokens[b*TT + t];
    float s = gamma[d] * rsqrtf(mvar[d] + 1e-3f);
    g_xn[idx] = (emb[(size_t)tok*EMBD + d] - mmean[d]) * s + beta[d];
}

__global__ void init_state()
{
    int i = blockIdx.x * blockDim.x + threadIdx.x;
    if (i < 2*BB*NU1) g_h1[i] = 0.f;
    if (i < 2*BB*NU2) g_h2[i] = 0.f;
    if (i < 4*32) { g_cnt1[i] = 0; g_gen1[i] = 0; g_cnt2[i] = 0; g_gen2[i] = 0; }
}

__global__ void copy_h(const float* __restrict__ src, float* __restrict__ dst, int n)
{
    int i = blockIdx.x * blockDim.x + threadIdx.x;
    if (i < n) dst[i] = src[i];
}

// transpose src [TT][U][BB] -> dst [BB][TT][U]
__global__ void transpose_tub(const float* __restrict__ src, float* __restrict__ dst, int U)
{
    __shared__ float s[32][33];
    int t = blockIdx.x, u0 = blockIdx.y*32, b0 = blockIdx.z*32;
    int xi = threadIdx.x, yj = threadIdx.y;
    for (int i = yj; i < 32; i += 8) {
        int u = u0 + i;
        if (u < U) s[i][xi] = src[((size_t)t*U + u)*BB + b0 + xi];
    }
    __syncthreads();
    for (int i = yj; i < 32; i += 8) {
        int u = u0 + xi;
        if (u < U) dst[((size_t)(b0 + i)*TT + t)*U + u] = s[xi][i];
    }
}

// ---------------- SGEMM1: 128x128 tile, 8x8/thread, f32x2 ----------------
__global__ void __launch_bounds__(256, 2)
sgemm128(const float* __restrict__ A, const float* __restrict__ Bw,
         const float* __restrict__ bias, float* __restrict__ C, int N, int K)
{
    constexpr int AP = 132, BP = 132;
    __shared__ float As[2][8][AP];
    __shared__ float Bs[2][8][BP];
    const int tid = threadIdx.x;
    const int col0 = blockIdx.x * 128;
    const int row0 = blockIdx.y * 128;
    const int tx = tid & 15, ty = tid >> 4;

    for (int i = tid; i < 2*8*BP; i += 256) (&Bs[0][0][0])[i] = 0.f;
    __syncthreads();

    const int bkk = tid >> 5, bnq = (tid & 31) * 4;
    const int bgc = col0 + bnq;
    uint32_t bs_s0 = (uint32_t)__cvta_generic_to_shared(&Bs[0][bkk][bnq]);
    uint32_t bs_s1 = (uint32_t)__cvta_generic_to_shared(&Bs[1][bkk][bnq]);

    float4 rA;
    auto loadA = [&](int k0) {
        int m = tid >> 1, kq = (tid & 1) * 4;
        rA = *reinterpret_cast<const float4*>(A + (size_t)(row0 + m)*K + k0 + kq);
    };
    auto stsA = [&](int buf) {
        int m = tid >> 1, kq = (tid & 1) * 4;
        As[buf][kq+0][m] = rA.x; As[buf][kq+1][m] = rA.y;
        As[buf][kq+2][m] = rA.z; As[buf][kq+3][m] = rA.w;
    };
    auto asyncB = [&](int k0, int buf) {
        if (bgc < N)
            cp_async16(buf ? bs_s1 : bs_s0, Bw + (size_t)(k0 + bkk)*N + bgc);
    };

    loadA(0);
    asyncB(0, 0);
    cp_commit();

    unsigned long long acc[4][8] = {};
    const int NC = K / 8;
    for (int c = 0; c < NC; c++) {
        int buf = c & 1;
        cp_wait0();
        stsA(buf);
        __syncthreads();
        if (c + 1 < NC) {
            loadA((c+1)*8);
            asyncB((c+1)*8, buf ^ 1);
            cp_commit();
        }
#pragma unroll
        for (int kk = 0; kk < 8; kk++) {
            ulonglong2 a01 = *reinterpret_cast<const ulonglong2*>(&As[buf][kk][ty*8]);
            ulonglong2 a23 = *reinterpret_cast<const ulonglong2*>(&As[buf][kk][ty*8 + 4]);
            float4 b0 = *reinterpret_cast<const float4*>(&Bs[buf][kk][tx*4]);
            float4 b1 = *reinterpret_cast<const float4*>(&Bs[buf][kk][64 + tx*4]);
            unsigned long long ap[4] = {a01.x, a01.y, a23.x, a23.y};
            unsigned long long bd[8];
            bd[0] = pack2(b0.x, b0.x); bd[1] = pack2(b0.y, b0.y);
            bd[2] = pack2(b0.z, b0.z); bd[3] = pack2(b0.w, b0.w);
            bd[4] = pack2(b1.x, b1.x); bd[5] = pack2(b1.y, b1.y);
            bd[6] = pack2(b1.z, b1.z); bd[7] = pack2(b1.w, b1.w);
#pragma unroll
            for (int r = 0; r < 4; r++)
#pragma unroll
                for (int cc = 0; cc < 8; cc++)
                    acc[r][cc] = fma2(ap[r], bd[cc], acc[r][cc]);
        }
        __syncthreads();
    }

#pragma unroll
    for (int r = 0; r < 4; r++) {
        size_t gr = row0 + ty*8 + r*2;
#pragma unroll
        for (int cc = 0; cc < 8; cc++) {
            int gc = col0 + (cc < 4 ? tx*4 + cc : 64 + tx*4 + (cc - 4));
            if (gc < N) {
                float2 v = unpack2(acc[r][cc]);
                float bv = bias[gc];
                C[gr*N + gc]       = v.x + bv;
                C[(gr + 1)*N + gc] = v.y + bv;
            }
        }
    }
}

// ================= fused persistent kernel: L1 (100 CTAs) + L2 (40 CTAs) =================
// L1: CTA = 16 units x 32 batches, groups of 25 CTAs per 32-batch tile (gen1 = producer flag).
// L2: CTA = 20 units x 32 batches, groups of 10; per step computes xw2 = out1(t)@W2 on the fly.
#define NTHR 320
#define L1_CTAS 100
#define FUSED_SMEM 230656

__global__ void __launch_bounds__(NTHR, 1)
fused_gru(const float* __restrict__ xw1, const float* __restrict__ Ur1,
          const float* __restrict__ br1, const float* __restrict__ W2,
          const float* __restrict__ Ur2, const float* __restrict__ b2full,
          const int* __restrict__ tokens,
          float* __restrict__ o1t, float* __restrict__ o2t,
          float* __restrict__ h1p, float* __restrict__ h2p)
{
    extern __shared__ float sm[];
    const int tid  = threadIdx.x;
    const int w    = tid >> 5;
    const int lane = tid & 31;

    if (blockIdx.x < L1_CTAS) {
        // ---------------- L1 role (R9-proven path) ----------------
        constexpr int UT = 16, KP = NU1 + 4, XS = 3*UT;
        float*    sU    = sm;                        // [48][404]
        float*    sH    = sU + 3*UT*KP;              // [32][404]
        float*    sX    = sH + 32*KP;                // [2][32][48]
        unsigned* sMask = (unsigned*)(sX + 2*32*XS); // [32][8]

        const int u0  = (blockIdx.x % 25) * UT;
        const int grp = blockIdx.x / 25;
        const int b0  = grp * 32;
        const int b   = b0 + lane;
        const int uu0 = u0 + w*2;

        for (int i = tid; i < 3*UT*NU1; i += NTHR) {
            int k = i / (3*UT), c = i % (3*UT);
            int g = c / UT, lu = c % UT;
            sU[(lu*3 + g)*KP + k] = Ur1[(size_t)k*(3*NU1) + g*NU1 + u0 + lu];
        }
        for (int i = tid; i < 32*8; i += NTHR) {
            int bb = i >> 3, wd = i & 7;
            unsigned m = 0;
            for (int j = 0; j < 32; j++)
                m |= (tokens[(b0 + bb)*TT + wd*32 + j] != 0 ? 1u : 0u) << j;
            sMask[bb*8 + wd] = m;
        }
        const uint32_t sX_s = (uint32_t)__cvta_generic_to_shared(sX);
        const uint32_t sH_s = (uint32_t)__cvta_generic_to_shared(sH);
        for (int i = tid; i < 32*(XS/4); i += NTHR) {
            int bb = i / (XS/4), q = i % (XS/4);
            int g = q / (UT/4), l4 = q % (UT/4);
            cp_async16(sX_s + (uint32_t)(bb*XS + g*UT + l4*4)*4,
                       xw1 + (size_t)(b0 + bb)*(3*NU1) + (size_t)g*NU1 + u0 + l4*4);
        }
        cp_commit();

        float bz[2], brr[2], bh[2];
#pragma unroll
        for (int j = 0; j < 2; j++) {
            bz[j]  = br1[uu0 + j];
            brr[j] = br1[NU1 + uu0 + j];
            bh[j]  = br1[2*NU1 + uu0 + j];
        }
        const float* hrow = sH + lane*KP;

        for (int t = 0; t < TT; t++) {
            const float* hg = h1p + (t & 1) * (BB*NU1);
            float*       hn = h1p + ((t + 1) & 1) * (BB*NU1);
            const float* sXc = sX + (t & 1)*32*XS;

            for (int i = tid; i < 32*(NU1/4); i += NTHR) {
                int bb = i / (NU1/4), kk = i % (NU1/4);
                cp_async16(sH_s + (uint32_t)(bb*KP + kk*4)*4,
                           hg + (size_t)(b0+bb)*NU1 + kk*4);
            }
            cp_commit();
            cp_wait0();
            __syncthreads();

            if (w < 8) {
                unsigned long long az[2] = {}, ar[2] = {}, ah[2] = {};
#pragma unroll 4
                for (int k = 0; k < NU1; k += 4) {
                    ulonglong2 h2 = *reinterpret_cast<const ulonglong2*>(hrow + k);
#pragma unroll
                    for (int j = 0; j < 2; j++) {
                        const float* ub = sU + ((w*2 + j)*3)*KP + k;
                        ulonglong2 uz = *reinterpret_cast<const ulonglong2*>(ub);
                        ulonglong2 ur = *reinterpret_cast<const ulonglong2*>(ub + KP);
                        ulonglong2 uh = *reinterpret_cast<const ulonglong2*>(ub + 2*KP);
                        az[j] = fma2(h2.x, uz.x, az[j]); az[j] = fma2(h2.y, uz.y, az[j]);
                        ar[j] = fma2(h2.x, ur.x, ar[j]); ar[j] = fma2(h2.y, ur.y, ar[j]);
                        ah[j] = fma2(h2.x, uh.x, ah[j]); ah[j] = fma2(h2.y, uh.y, ah[j]);
                    }
                }
                const int mk = (sMask[lane*8 + (t >> 5)] >> (t & 31)) & 1;
                float hv[2];
#pragma unroll
                for (int j = 0; j < 2; j++) {
                    float vz = hsum2(az[j]), vr = hsum2(ar[j]), vh = hsum2(ah[j]);
                    int lu = w*2 + j;
                    float xz = sXc[lane*XS + lu];
                    float xr = sXc[lane*XS + UT + lu];
                    float xh = sXc[lane*XS + 2*UT + lu];
                    float z  = 1.f / (1.f + __expf(-(xz + vz + bz[j])));
                    float r  = 1.f / (1.f + __expf(-(xr + vr + brr[j])));
                    float hh = tanhf(xh + r * (vh + bh[j]));
                    float hold = hrow[uu0 + j];
                    float hnew = z*hold + (1.f - z)*hh;
                    hv[j] = mk ? hnew : hold;
                }
                *reinterpret_cast<float2*>(hn + (size_t)b*NU1 + uu0) = make_float2(hv[0], hv[1]);
                o1t[((size_t)t*NU1 + uu0    )*BB + b] = hv[0];
                o1t[((size_t)t*NU1 + uu0 + 1)*BB + b] = hv[1];
            }

            if (t + 1 < TT) {
                uint32_t dst = sX_s + (uint32_t)(((t+1) & 1)*32*XS)*4;
                for (int i = tid; i < 32*(XS/4); i += NTHR) {
                    int bb = i / (XS/4), q = i % (XS/4);
                    int g = q / (UT/4), l4 = q % (UT/4);
                    cp_async16(dst + (uint32_t)(bb*XS + g*UT + l4*4)*4,
                               xw1 + ((size_t)(t+1)*BB + b0 + bb)*(size_t)(3*NU1)
                                   + (size_t)g*NU1 + u0 + l4*4);
                }
                cp_commit();
            }

            __syncthreads();
            if (tid == 0) {
                unsigned target = (unsigned)(t + 1);
                unsigned arr = atom_arrive(g_cnt1 + grp*32);
                if (arr == 24u) {
                    st_relaxed(g_cnt1 + grp*32, 0);
                    st_release(g_gen1 + grp*32, target);
                } else {
                    while (ld_acquire(g_gen1 + grp*32) < target) { }
                }
            }
            __syncthreads();
        }
    } else {
        // ---------------- L2 role: on-the-fly projection + recurrence ----------------
        constexpr int UT2 = 20, COLS = 3*UT2;        // 60 cols, col = u*3 + g
        constexpr int KP2 = NU2 + 4;                 // 204
        constexpr int KW1 = NU1 + 4;                 // 404 (proj K pad)
        float* sW2 = sm;                             // [60][404]
        float* sU2 = sW2 + COLS*KW1;                 // [60][204]
        float* sO1 = sU2 + COLS*KP2;                 // [400][36]
        float* sH2 = sO1 + NU1*36;                   // [32][204]
        unsigned* sMask = (unsigned*)(sH2 + 32*KP2); // [32][8]

        const int ci  = blockIdx.x - L1_CTAS;        // 0..39
        const int u20 = (ci % 10) * UT2;             // global unit base
        const int grp = ci / 10;
        const int b0  = grp * 32;
        const int b   = b0 + lane;

        // one-time: W2/U2 slices (u-major cols), mask
        for (int i = tid; i < COLS*NU1; i += NTHR) {
            int k = i / COLS, c = i % COLS;
            int ul = c / 3, g = c % 3;
            sW2[c*KW1 + k] = W2[(size_t)k*(3*NU2) + g*NU2 + u20 + ul];
        }
        for (int i = tid; i < COLS*NU2; i += NTHR) {
            int k = i / COLS, c = i % COLS;
            int ul = c / 3, g = c % 3;
            sU2[c*KP2 + k] = Ur2[(size_t)k*(3*NU2) + g*NU2 + u20 + ul];
        }
        for (int i = tid; i < 32*8; i += NTHR) {
            int bb = i >> 3, wd = i & 7;
            unsigned m = 0;
            for (int j = 0; j < 32; j++)
                m |= (tokens[(b0 + bb)*TT + wd*32 + j] != 0 ? 1u : 0u) << j;
            sMask[bb*8 + wd] = m;
        }

        // per-lane biases for this warp's 2 units (col base = w*6)
        float bi[6], brc[6];
#pragma unroll
        for (int j = 0; j < 6; j++) {
            int c = w*6 + j;
            int ul = c / 3, g = c % 3;
            bi[j]  = b2full[g*NU2 + u20 + ul];
            brc[j] = b2full[3*NU2 + g*NU2 + u20 + ul];
        }

        const uint32_t sO1_s = (uint32_t)__cvta_generic_to_shared(sO1);
        const uint32_t sH2_s = (uint32_t)__cvta_generic_to_shared(sH2);
        const float* h2row = sH2 + lane*KP2;

        for (int t = 0; t < TT; t++) {
            // wait for L1 group to publish out1(t)
            if (tid == 0) {
                unsigned need = (unsigned)(t + 1);
                while (ld_acquire(g_gen1 + grp*32) < need) { }
            }
            __syncthreads();

            const float* hg = h2p + (t & 1) * (BB*NU2);
            float*       hn = h2p + ((t + 1) & 1) * (BB*NU2);

            // stage out1(t) slice [400][32] and h2(t) [32][200]
            for (int i = tid; i < NU1*8; i += NTHR) {
                int k = i >> 3, q = i & 7;
                cp_async16(sO1_s + (uint32_t)(k*36 + q*4)*4,
                           o1t + ((size_t)t*NU1 + k)*BB + b0 + q*4);
            }
            for (int i = tid; i < 32*(NU2/4); i += NTHR) {
                int bb = i / (NU2/4), kk = i % (NU2/4);
                cp_async16(sH2_s + (uint32_t)(bb*KP2 + kk*4)*4,
                           hg + (size_t)(b0+bb)*NU2 + kk*4);
            }
            cp_commit();
            cp_wait0();
            __syncthreads();

            unsigned long long accP[6] = {}, accR[6] = {};
            // projection: xw2 = out1(t) @ W2slice  (K=400)
#pragma unroll 2
            for (int k = 0; k < NU1; k += 4) {
                float o0 = sO1[(k+0)*36 + lane];
                float o1 = sO1[(k+1)*36 + lane];
                float o2 = sO1[(k+2)*36 + lane];
                float o3 = sO1[(k+3)*36 + lane];
                unsigned long long p01 = pack2(o0, o1), p23 = pack2(o2, o3);
#pragma unroll
                for (int j = 0; j < 6; j++) {
                    const float* wp = sW2 + (w*6 + j)*KW1 + k;
                    ulonglong2 wv = *reinterpret_cast<const ulonglong2*>(wp);
                    accP[j] = fma2(p01, wv.x, accP[j]);
                    accP[j] = fma2(p23, wv.y, accP[j]);
                }
            }
            // recurrence: h2(t) @ U2slice  (K=200)
#pragma unroll 2
            for (int k = 0; k < NU2; k += 4) {
                ulonglong2 h2v = *reinterpret_cast<const ulonglong2*>(h2row + k);
#pragma unroll
                for (int j = 0; j < 6; j++) {
                    const float* up = sU2 + (w*6 + j)*KP2 + k;
                    ulonglong2 uv = *reinterpret_cast<const ulonglong2*>(up);
                    accR[j] = fma2(h2v.x, uv.x, accR[j]);
                    accR[j] = fma2(h2v.y, uv.y, accR[j]);
                }
            }

            const int mk = (sMask[lane*8 + (t >> 5)] >> (t & 31)) & 1;
#pragma unroll
            for (int je = 0; je < 2; je++) {
                int ug = u20 + 2*w + je;
                float Pz = hsum2(accP[je*3+0]) + bi[je*3+0];
                float Pr = hsum2(accP[je*3+1]) + bi[je*3+1];
                float Ph = hsum2(accP[je*3+2]) + bi[je*3+2];
                float Rz = hsum2(accR[je*3+0]) + brc[je*3+0];
                float Rr = hsum2(accR[je*3+1]) + brc[je*3+1];
                float Rh = hsum2(accR[je*3+2]) + brc[je*3+2];
                float z  = 1.f / (1.f + __expf(-(Pz + Rz)));
                float r  = 1.f / (1.f + __expf(-(Pr + Rr)));
                float hh = tanhf(Ph + r * Rh);
                float hold = h2row[ug];
                float hnew = z*hold + (1.f - z)*hh;
                float hv = mk ? hnew : hold;
                hn[(size_t)b*NU2 + ug] = hv;
                o2t[((size_t)t*NU2 + ug)*BB + b] = hv;
            }

            __syncthreads();
            if (tid == 0) {
                unsigned target = (unsigned)(t + 1);
                unsigned arr = atom_arrive(g_cnt2 + grp*32);
                if (arr == 9u) {
                    st_relaxed(g_cnt2 + grp*32, 0);
                    st_release(g_gen2 + grp*32, target);
                } else {
                    while (ld_acquire(g_gen2 + grp*32) < target) { }
                }
            }
            __syncthreads();
        }
    }
}

extern "C" void kernel_launch(void* const* d_in, const int* in_sizes, int n_in,
                              void* d_out, int out_size)
{
    const int*   tokens = (const int*)  d_in[0];
    const float* emb    = (const float*)d_in[1];
    const float* gamma  = (const float*)d_in[2];
    const float* beta   = (const float*)d_in[3];
    const float* mmean  = (const float*)d_in[4];
    const float* mvar   = (const float*)d_in[5];
    const float* W1     = (const float*)d_in[6];
    const float* Ur1    = (const float*)d_in[7];
    const float* b1     = (const float*)d_in[8];
    const float* W2     = (const float*)d_in[9];
    const float* Ur2    = (const float*)d_in[10];
    const float* b2     = (const float*)d_in[11];

    float* out  = (float*)d_out;
    float* out2 = out + OUT2_OFF;
    float* out1 = out + OUT1_OFF;
    float* h2o  = out + H2_OFF;
    float* h1o  = out + H1_OFF;

    void *p_xn, *p_xw1, *p_o1t, *p_o2t, *p_h1, *p_h2;
    cudaGetSymbolAddress(&p_xn,  g_xn);
    cudaGetSymbolAddress(&p_xw1, g_xw1);
    cudaGetSymbolAddress(&p_o1t, g_o1t);
    cudaGetSymbolAddress(&p_o2t, g_o2t);
    cudaGetSymbolAddress(&p_h1,  g_h1);
    cudaGetSymbolAddress(&p_h2,  g_h2);
    float* xn  = (float*)p_xn;
    float* xw1 = (float*)p_xw1;
    float* o1t = (float*)p_o1t;
    float* o2t = (float*)p_o2t;
    float* h1p = (float*)p_h1;
    float* h2p = (float*)p_h2;

    cudaFuncSetAttribute(fused_gru, cudaFuncAttributeMaxDynamicSharedMemorySize, FUSED_SMEM);

    embed_bn<<<(BB*TT*EMBD + 255)/256, 256>>>(tokens, emb, gamma, beta, mmean, mvar);
    init_state<<<(2*BB*NU1 + 255)/256, 256>>>();

    // xw1 = xn @ W1 + b1[0]
    sgemm128<<<dim3((3*NU1 + 127)/128, (BB*TT)/128), 256>>>(xn, W1, b1, xw1, 3*NU1, EMBD);

    // fused persistent L1+L2
    fused_gru<<<140, NTHR, FUSED_SMEM>>>(xw1, Ur1, b1 + 3*NU1, W2, Ur2, b2,
                                         tokens, o1t, o2t, h1p, h2p);

    copy_h<<<(BB*NU1 + 255)/256, 256>>>(h1p, h1o, BB*NU1);   // T even -> buf 0
    copy_h<<<(BB*NU2 + 255)/256, 256>>>(h2p, h2o, BB*NU2);
    transpose_tub<<<dim3(TT, (NU1 + 31)/32, BB/32), dim3(32, 8)>>>(o1t, out1, NU1);
    transpose_tub<<<dim3(TT, (NU2 + 31)/32, BB/32), dim3(32, 8)>>>(o2t, out2, NU2);
}